// round 2
// baseline (speedup 1.0000x reference)
#include <cuda_runtime.h>
#include <cstdint>

#define BB 128
#define CC 32
#define LL 4096
#define LT 8            // l positions per CTA (one 32B sector of the l-dim)
#define BCHUNK 32       // batch rows staged per chunk
#define NCHUNK (BB / BCHUNK)
#define THREADS 256     // 8 warps = 8 l positions

#define XS_FLOATS (BCHUNK * LT * CC)        // 8192 floats = 32 KB : x_s[b][l][c]
#define OS_PAD 9
#define OS_FLOATS (BCHUNK * CC * OS_PAD)    // 9216 floats = 36 KB : o_s[b][d][9]
#define SMEM_BYTES ((XS_FLOATS + OS_FLOATS) * 4)

__device__ __forceinline__ unsigned long long pack_f32x2(float lo, float hi) {
    unsigned long long r;
    asm("mov.b64 %0, {%1, %2};" : "=l"(r) : "r"(__float_as_uint(lo)), "r"(__float_as_uint(hi)));
    return r;
}

__device__ __forceinline__ void unpack_f32x2(unsigned long long v, float& lo, float& hi) {
    unsigned int a, b;
    asm("mov.b64 {%0, %1}, %2;" : "=r"(a), "=r"(b) : "l"(v));
    lo = __uint_as_float(a);
    hi = __uint_as_float(b);
}

__device__ __forceinline__ void fma2(unsigned long long& d, unsigned long long a,
                                     unsigned long long b, unsigned long long c) {
    asm("fma.rn.f32x2 %0, %1, %2, %3;" : "=l"(d) : "l"(a), "l"(b), "l"(c));
}

__device__ __forceinline__ unsigned long long add2(unsigned long long a, unsigned long long b) {
    unsigned long long d;
    asm("add.rn.f32x2 %0, %1, %2;" : "=l"(d) : "l"(a), "l"(b));
    return d;
}

__global__ void __launch_bounds__(THREADS, 1)
dyna_dec_kernel(const float* __restrict__ x, const float* __restrict__ weight,
                const float* __restrict__ bias, float* __restrict__ out) {
    extern __shared__ float smem[];
    float* x_s = smem;              // [BCHUNK][LT][CC]
    float* o_s = smem + XS_FLOATS;  // [BCHUNK][CC][OS_PAD]

    const int tid  = threadIdx.x;
    const int w    = tid >> 5;   // warp index = local l
    const int lane = tid & 31;   // = output channel d
    const int l0   = blockIdx.x * LT;
    const int lg   = l0 + w;     // this warp's global l

    // ---- Per-warp weight column: W2[p] = {W[l][2p][d], W[l][2p+1][d]} ----
    unsigned long long W2[CC / 2];
    {
        const float* wp = weight + (size_t)lg * CC * CC + lane;  // stride CC between c
        #pragma unroll
        for (int p = 0; p < CC / 2; p++) {
            float a = __ldg(wp + (2 * p) * CC);      // coalesced across lanes
            float b = __ldg(wp + (2 * p + 1) * CC);
            W2[p] = pack_f32x2(a, b);
        }
    }
    const float bi = __ldg(bias + lg * CC + lane);

    for (int ch = 0; ch < NCHUNK; ch++) {
        __syncthreads();  // previous chunk's compute (x_s reads) done

        // ---- Stage x[b, c, l0..l0+7] -> x_s[b][l][c] (transpose) ----
        #pragma unroll
        for (int it = 0; it < (BCHUNK * CC) / THREADS; it++) {
            int r  = it * THREADS + tid;
            int bl = r >> 5;        // local batch row
            int c  = r & 31;        // channel (== lane -> conflict-free STS banks)
            const float4* g =
                (const float4*)(x + ((size_t)((ch * BCHUNK + bl) * CC + c)) * LL + l0);
            float4 v0 = g[0];
            float4 v1 = g[1];
            float* d0 = x_s + (bl * LT) * CC + c;   // stride CC between l — bank = c
            d0[0 * CC] = v0.x; d0[1 * CC] = v0.y; d0[2 * CC] = v0.z; d0[3 * CC] = v0.w;
            d0[4 * CC] = v1.x; d0[5 * CC] = v1.y; d0[6 * CC] = v1.z; d0[7 * CC] = v1.w;
        }
        __syncthreads();

        // ---- Compute: warp w handles l = l0+w; lane = d ----
        #pragma unroll 2
        for (int bl = 0; bl < BCHUNK; bl++) {
            const double2* xp = (const double2*)(x_s + (bl * LT + w) * CC);  // 128B aligned
            unsigned long long a0 = 0ull, a1 = 0ull;  // {0,0} packed accumulators
            #pragma unroll
            for (int q = 0; q < 8; q++) {
                double2 v = xp[q];  // covers c = 4q .. 4q+3 (broadcast LDS.128)
                unsigned long long x01 = __double_as_longlong(v.x);  // {x[4q],   x[4q+1]}
                unsigned long long x23 = __double_as_longlong(v.y);  // {x[4q+2], x[4q+3]}
                fma2(a0, x01, W2[2 * q + 0], a0);
                fma2(a1, x23, W2[2 * q + 1], a1);
            }
            unsigned long long s = add2(a0, a1);
            float lo, hi;
            unpack_f32x2(s, lo, hi);
            // o_s[bl][d][w] — stride 9 across lanes: conflict-free
            o_s[(bl * CC + lane) * OS_PAD + w] = lo + hi + bi;
        }
        __syncthreads();

        // ---- Copy out: 8 consecutive l per (b,d) row -> coalesced 32B stores ----
        #pragma unroll
        for (int it = 0; it < (BCHUNK * CC * LT) / THREADS; it++) {
            int i   = it * THREADS + tid;
            int row = i >> 3;   // (bl*32 + d)
            int li  = i & 7;
            float val = o_s[row * OS_PAD + li];
            int bl = row >> 5;
            int d  = row & 31;
            out[((size_t)((ch * BCHUNK + bl) * CC + d)) * LL + l0 + li] = val;
        }
    }
}

extern "C" void kernel_launch(void* const* d_in, const int* in_sizes, int n_in,
                              void* d_out, int out_size) {
    const float* x      = (const float*)d_in[0];
    // d_in[1] = px, unused by the reference
    const float* weight = (const float*)d_in[2];
    const float* bias   = (const float*)d_in[3];
    float* out          = (float*)d_out;

    cudaFuncSetAttribute(dyna_dec_kernel, cudaFuncAttributeMaxDynamicSharedMemorySize,
                         SMEM_BYTES);

    dim3 grid(LL / LT);    // 512 CTAs
    dim3 block(THREADS);
    dyna_dec_kernel<<<grid, block, SMEM_BYTES>>>(x, weight, bias, out);
}

// round 3
// speedup vs baseline: 1.2330x; 1.2330x over previous
#include <cuda_runtime.h>
#include <cstdint>

#define BB 128
#define CC 32
#define LL 4096
#define LT 16           // l positions per CTA
#define BCH 8           // batch rows per chunk
#define NCH 4           // chunks per CTA (32 b per CTA)
#define BSPLIT 4        // b-splits across CTAs
#define THREADS 512     // 16 warps, warp w handles l = l0 + w

// x_s: [BCH][LT][CC] with XOR-swizzled c-chunks; o_s: [BCH*CC rows][17]
#define XS_FLOATS (BCH * LT * CC)     // 4096
#define OS_PAD 17
#define OS_FLOATS (BCH * CC * OS_PAD) // 4352

__device__ __forceinline__ unsigned long long pack_f32x2(float lo, float hi) {
    unsigned long long r;
    asm("mov.b64 %0, {%1, %2};" : "=l"(r) : "r"(__float_as_uint(lo)), "r"(__float_as_uint(hi)));
    return r;
}
__device__ __forceinline__ void unpack_f32x2(unsigned long long v, float& lo, float& hi) {
    unsigned int a, b;
    asm("mov.b64 {%0, %1}, %2;" : "=r"(a), "=r"(b) : "l"(v));
    lo = __uint_as_float(a);
    hi = __uint_as_float(b);
}
__device__ __forceinline__ void fma2(unsigned long long& d, unsigned long long a,
                                     unsigned long long b, unsigned long long c) {
    asm("fma.rn.f32x2 %0, %1, %2, %3;" : "=l"(d) : "l"(a), "l"(b), "l"(c));
}
__device__ __forceinline__ unsigned long long add2(unsigned long long a, unsigned long long b) {
    unsigned long long d;
    asm("add.rn.f32x2 %0, %1, %2;" : "=l"(d) : "l"(a), "l"(b));
    return d;
}

__global__ void __launch_bounds__(THREADS, 2)
dyna_dec_kernel(const float* __restrict__ x, const float* __restrict__ weight,
                const float* __restrict__ bias, float* __restrict__ out) {
    __shared__ __align__(16) float x_s[XS_FLOATS];
    __shared__ __align__(16) float o_s[OS_FLOATS];

    const int tid  = threadIdx.x;
    const int w    = tid >> 5;       // warp index = local l
    const int lane = tid & 31;       // output channel d (compute phase)
    const int l0   = blockIdx.x * LT;
    const int b0   = blockIdx.y * (BCH * NCH);
    const int lg   = l0 + w;

    // ---- Per-warp weight column: W2[p] = {W[lg][2p][lane], W[lg][2p+1][lane]} ----
    unsigned long long W2[CC / 2];
    {
        const float* wp = weight + (size_t)lg * CC * CC + lane;
        #pragma unroll
        for (int p = 0; p < CC / 2; p++) {
            float a = __ldg(wp + (2 * p) * CC);
            float b = __ldg(wp + (2 * p + 1) * CC);
            W2[p] = pack_f32x2(a, b);
        }
    }
    const float bi = __ldg(bias + lg * CC + lane);

    const int swc = (w >> 1) & 6;    // compute-side x_s chunk swizzle for l = w

    float4 pf0, pf1;                 // prefetch registers (2 tasks/thread)

    // ---------- prologue: load + stage chunk 0 ----------
    {
        int t0 = tid,           ls0 = t0 & 3, r0 = t0 >> 2;
        int t1 = THREADS + tid, ls1 = t1 & 3, r1 = t1 >> 2;
        pf0 = *(const float4*)(x + ((size_t)((b0 + (r0 >> 5)) * CC + (r0 & 31))) * LL + l0 + 4 * ls0);
        pf1 = *(const float4*)(x + ((size_t)((b0 + (r1 >> 5)) * CC + (r1 & 31))) * LL + l0 + 4 * ls1);
    }

    for (int ch = 0; ch < NCH; ch++) {
        // ---- stage prefetched chunk into x_s (swizzled, conflict-free STS) ----
        #pragma unroll
        for (int it = 0; it < 2; it++) {
            int t = it * THREADS + tid;
            int lseg = t & 3;
            int r = t >> 2;
            int b = r >> 5, c = r & 31;
            int slot = ((c >> 2) ^ (2 * lseg)) & 7;
            float* dst = x_s + b * (LT * CC) + (4 * lseg) * CC + slot * 4 + (c & 3);
            float4 v = it == 0 ? pf0 : pf1;
            dst[0 * CC] = v.x; dst[1 * CC] = v.y; dst[2 * CC] = v.z; dst[3 * CC] = v.w;
        }
        __syncthreads();

        // ---- prefetch next chunk (LDG latency hidden behind compute) ----
        if (ch + 1 < NCH) {
            int bc = b0 + (ch + 1) * BCH;
            int t0 = tid,           ls0 = t0 & 3, r0 = t0 >> 2;
            int t1 = THREADS + tid, ls1 = t1 & 3, r1 = t1 >> 2;
            pf0 = *(const float4*)(x + ((size_t)((bc + (r0 >> 5)) * CC + (r0 & 31))) * LL + l0 + 4 * ls0);
            pf1 = *(const float4*)(x + ((size_t)((bc + (r1 >> 5)) * CC + (r1 & 31))) * LL + l0 + 4 * ls1);
        }

        // ---- compute: warp w handles l = l0 + w; lane = d ----
        {
            const int seg = w >> 2, j = w & 3;
            #pragma unroll
            for (int b = 0; b < BCH; b++) {
                const char* base = (const char*)(x_s + b * (LT * CC) + w * CC);
                unsigned long long a0 = 0ull, a1 = 0ull;
                #pragma unroll
                for (int u = 0; u < 8; u++) {
                    // slot (u ^ swc) holds channels 4u..4u+3 (broadcast LDS.128)
                    ulonglong2 v = *(const ulonglong2*)(base + (((u ^ swc) & 7) << 4));
                    fma2(a0, v.x, W2[2 * u + 0], a0);
                    fma2(a1, v.y, W2[2 * u + 1], a1);
                }
                unsigned long long s = add2(a0, a1);
                float lo, hi;
                unpack_f32x2(s, lo, hi);
                int row = b * CC + lane;
                int segp = (seg + ((row >> 1) & 2)) & 3;   // additive seg swizzle
                o_s[row * OS_PAD + 4 * segp + j] = lo + hi + bi;  // conflict-free STS
            }
        }
        __syncthreads();

        // ---- output pass: gather rows from o_s, vectorized STG ----
        #pragma unroll
        for (int it = 0; it < 2; it++) {
            int t = it * THREADS + tid;
            int s = t & 3;
            int r = t >> 2;                 // row = b*32 + d
            int b = r >> 5, d = r & 31;
            int segp = (s + ((r >> 1) & 2)) & 3;
            const float* src = o_s + r * OS_PAD + 4 * segp;
            float4 v;
            v.x = src[0]; v.y = src[1]; v.z = src[2]; v.w = src[3];
            *(float4*)(out + ((size_t)((b0 + ch * BCH + b) * CC + d)) * LL + l0 + 4 * s) = v;
        }
        __syncthreads();
    }
}

extern "C" void kernel_launch(void* const* d_in, const int* in_sizes, int n_in,
                              void* d_out, int out_size) {
    const float* x      = (const float*)d_in[0];
    // d_in[1] = px, unused by the reference
    const float* weight = (const float*)d_in[2];
    const float* bias   = (const float*)d_in[3];
    float* out          = (float*)d_out;

    dim3 grid(LL / LT, BSPLIT);   // (256, 4) = 1024 CTAs
    dim3 block(THREADS);
    dyna_dec_kernel<<<grid, block>>>(x, weight, bias, out);
}